// round 7
// baseline (speedup 1.0000x reference)
#include <cuda_runtime.h>

// RankDPO loss, B=8192, K=64. Single fused kernel (R6 loop, balanced grid).
// Grid = 1184 blocks (148 SMs x 8) x 224 threads (7 warps) -> exactly 56
// warps per SM, no wave quantization. 1184*7 = 8288 warp-rows; the last 96
// warps run on a clamped row and contribute zero.

#define WARPS_PER_BLOCK 7
#define THREADS 224                          // 7 warps
#define NUM_BLOCKS 1184                      // 148 * 8
#define NROWS 8192
#define INV_PAIR_COUNT (1.0f / 16515072.0f)  // 8192 * 2016
#define LOG2E 1.4426950408889634f
#define LN2   0.6931471805599453f

static __device__ float g_partials[NUM_BLOCKS];
static __device__ unsigned int g_ticket = 0;

typedef unsigned long long u64;

static __device__ __forceinline__ float ex2f(float x) {
    float y; asm("ex2.approx.f32 %0, %1;" : "=f"(y) : "f"(x)); return y;
}
static __device__ __forceinline__ float lg2f(float x) {
    float y; asm("lg2.approx.f32 %0, %1;" : "=f"(y) : "f"(x)); return y;
}
static __device__ __forceinline__ u64 packf2(float lo, float hi) {
    u64 r; asm("mov.b64 %0, {%1, %2};" : "=l"(r) : "f"(lo), "f"(hi)); return r;
}
static __device__ __forceinline__ void unpackf2(float& lo, float& hi, u64 v) {
    asm("mov.b64 {%0, %1}, %2;" : "=f"(lo), "=f"(hi) : "l"(v));
}
static __device__ __forceinline__ u64 addx2(u64 a, u64 b) {
    u64 r; asm("add.rn.f32x2 %0, %1, %2;" : "=l"(r) : "l"(a), "l"(b)); return r;
}
static __device__ __forceinline__ u64 mulx2(u64 a, u64 b) {
    u64 r; asm("mul.rn.f32x2 %0, %1, %2;" : "=l"(r) : "l"(a), "l"(b)); return r;
}

__global__ __launch_bounds__(THREADS, 8)
void rankdpo_fused(const float* __restrict__ S,
                   const float* __restrict__ R,
                   float* __restrict__ out) {
    __shared__ __align__(16) float4 Ptab[WARPS_PER_BLOCK][64];
    __shared__ __align__(8)  float2 Qtab[WARPS_PER_BLOCK][64];
    __shared__ __align__(16) float  rsh[WARPS_PER_BLOCK][64];
    __shared__ float wsum[WARPS_PER_BLOCK];
    __shared__ float red[256];
    __shared__ int   isLast;

    const int warp = threadIdx.x >> 5;
    const int lane = threadIdx.x & 31;
    const int rowRaw = blockIdx.x * WARPS_PER_BLOCK + warp;
    const bool valid = rowRaw < NROWS;
    const int row = valid ? rowRaw : 0;       // clamped; contribution zeroed

    const float* srow = S + row * 64;
    const float* rrow = R + row * 64;
    const float s0 = srow[lane];
    const float s1 = srow[lane + 32];
    const float r0 = rrow[lane];
    const float r1 = rrow[lane + 32];

    float* rw = rsh[warp];
    rw[lane]      = r0;
    rw[lane + 32] = r1;
    __syncwarp();

    // ---- rank: count strictly-greater rewards (ties ~2^-23/pair; tied pairs
    //      have dg=0 -> delta=0, so dropped tie-break is harmless) ----
    int c0 = 0, c1 = 0;
    const float4* rv = (const float4*)rw;
    #pragma unroll
    for (int q = 0; q < 16; q++) {
        const float4 v = rv[q];
        c0 += (v.x > r0) + (v.y > r0) + (v.z > r0) + (v.w > r0);
        c1 += (v.x > r1) + (v.y > r1) + (v.z > r1) + (v.w > r1);
    }
    const float d0 = __fdividef(1.f, __logf((float)(c0 + 2)));
    const float d1 = __fdividef(1.f, __logf((float)(c1 + 2)));
    const float g0 = 2.f * r0 - 1.f;
    const float g1 = 2.f * r1 - 1.f;
    const float sL0 = s0 * LOG2E;   // lg2-domain score
    const float sL1 = s1 * LOG2E;

    // interleaved tables: entry m serves pair (m,.) and the (m+32)-side pair
    Ptab[warp][lane]      = make_float4(sL0, sL1, g0, g1);
    Ptab[warp][lane + 32] = make_float4(sL1, sL0, g1, g0);
    Qtab[warp][lane]      = make_float2(d0, d1);
    Qtab[warp][lane + 32] = make_float2(d1, d0);
    __syncwarp();

    const u64 negS2 = packf2(-sL0, -sL1);
    const u64 negG2 = packf2(-g0, -g1);
    const u64 negD2 = packf2(-d0, -d1);

    const float4* Pb = &Ptab[warp][lane];
    const float2* Qb = &Qtab[warp][lane];

    float acc0 = 0.f;   // pair-A softplus_lg2 terms
    float acc1 = 0.f;   // pair-B unoriented softplus_lg2 terms
    float accC = 0.f;   // pair-B wrapped correction: sum delta*x (lg2 domain)
    #pragma unroll
    for (int k = 1; k < 32; k++) {
        const u64* pv = (const u64*)(Pb + k);
        const u64 sP = pv[0];                 // {sL[m], sL[(m+32)&63]}
        const u64 gP = pv[1];                 // {g[m],  g[(m+32)&63]}
        const u64 dP = *(const u64*)(Qb + k); // {d[m],  d[(m+32)&63]}

        const u64 x2     = addx2(sP, negS2);  // s_partner - s_own (lg2 dom)
        const u64 dg2    = addx2(gP, negG2);
        const u64 dd2    = addx2(dP, negD2);
        const u64 delta2 = mulx2(dg2, dd2);   // >= 0 by monotonicity, no abs

        float xA, xB, dtA, dtB;
        unpackf2(xA, xB, x2);
        unpackf2(dtA, dtB, delta2);

        // pair A: partner index lane+k > lane always -> oriented as-is
        const float lA = lg2f(1.f + ex2f(xA));
        acc0 = fmaf(dtA, lA, acc0);

        // pair B: unoriented softplus; wrapped (lane+k>=32 -> partner < own)
        // oriented value = lB - xB, folded in via the correction accumulator
        const float lB = lg2f(1.f + ex2f(xB));
        acc1 = fmaf(dtB, lB, acc1);
        if (lane + k >= 32) accC = fmaf(dtB, xB, accC);
    }
    {   // gap-32 pair (lane, lane+32): i = lane+32 > j = lane
        const float delta = (g1 - g0) * (d1 - d0);   // >= 0
        acc0 = fmaf(delta, lg2f(1.f + ex2f(sL1 - sL0)), acc0);
    }
    float acc = (acc0 + acc1 - accC) * LN2;
    if (!valid) acc = 0.f;

    // ---- warp reduce ----
    #pragma unroll
    for (int o = 16; o; o >>= 1)
        acc += __shfl_xor_sync(0xffffffffu, acc, o);
    if (lane == 0) wsum[warp] = acc;
    __syncthreads();

    if (threadIdx.x == 0) {
        float s = 0.f;
        #pragma unroll
        for (int w = 0; w < WARPS_PER_BLOCK; w++) s += wsum[w];
        g_partials[blockIdx.x] = s;
        __threadfence();
        const unsigned tk = atomicAdd(&g_ticket, 1u);
        isLast = (tk == (unsigned)(gridDim.x - 1));
    }
    __syncthreads();

    // ---- last block: deterministic fixed-order reduction of 1184 partials ----
    if (isLast) {
        const int tid = threadIdx.x;
        float v = 0.f;
        #pragma unroll
        for (int i = 0; i < 6; i++) {               // 6*224 = 1344 >= 1184
            const int idx = tid + i * THREADS;
            if (idx < NUM_BLOCKS) v += g_partials[idx];
        }
        red[tid] = v;
        if (tid < 32) red[tid + THREADS] = 0.f;     // pad 224..255
        __syncthreads();
        #pragma unroll
        for (int stride = 128; stride > 0; stride >>= 1) {
            if (tid < stride) red[tid] += red[tid + stride];
            __syncthreads();
        }
        if (tid == 0) {
            out[0] = red[0] * INV_PAIR_COUNT;
            g_ticket = 0;   // reset for graph replay
        }
    }
}

extern "C" void kernel_launch(void* const* d_in, const int* in_sizes, int n_in,
                              void* d_out, int out_size) {
    (void)in_sizes; (void)n_in; (void)out_size;
    const float* s = (const float*)d_in[0];   // policy_logps
    const float* r = (const float*)d_in[1];   // reward_scores
    rankdpo_fused<<<NUM_BLOCKS, THREADS>>>(s, r, (float*)d_out);
}